// round 1
// baseline (speedup 1.0000x reference)
#include <cuda_runtime.h>

#define Bsz 4
#define Tsz 2048
#define Csz 1024
#define Hn  16
#define Dh  64
#define BT  (Bsz * Tsz)     /* 8192 */
#define N3  (3 * Csz)       /* 3072 */

// Scratch (allocation-free rule: __device__ globals)
__device__ float g_q[Bsz * Hn * Tsz * Dh];   // [B,H,T,D]
__device__ float g_k[Bsz * Hn * Tsz * Dh];
__device__ float g_v[Bsz * Hn * Tsz * Dh];
__device__ float g_y[BT * Csz];              // [B,T,C] attention output

// ---------------------------------------------------------------------------
// GEMM 1: qkv = x @ w_attn + b_attn, scattered into g_q/g_k/g_v ([B,H,T,D])
// 128x128x8 tile, 256 threads, 8x8 per thread.
// ---------------------------------------------------------------------------
__global__ __launch_bounds__(256) void qkv_gemm(const float* __restrict__ A,
                                                const float* __restrict__ Bw,
                                                const float* __restrict__ bias)
{
    __shared__ float As[8][128];
    __shared__ float Bs[8][128];

    const int tid = threadIdx.x;
    const int bm = blockIdx.y * 128;
    const int bn = blockIdx.x * 128;
    const int tr = (tid >> 4) * 8;    // 0..120
    const int tc = (tid & 15) * 8;    // 0..120

    float acc[8][8];
#pragma unroll
    for (int i = 0; i < 8; i++)
#pragma unroll
        for (int j = 0; j < 8; j++) acc[i][j] = 0.f;

    const int arow = tid >> 1;            // 0..127
    const int acol = (tid & 1) * 4;       // 0 or 4
    const int brow = tid >> 5;            // 0..7
    const int bcol = (tid & 31) * 4;      // 0..124

    const float* Ap = A + (bm + arow) * Csz + acol;
    const float* Bp = Bw + brow * N3 + bn + bcol;

    for (int k0 = 0; k0 < Csz; k0 += 8) {
        float4 a4 = *(const float4*)(Ap + k0);
        float4 b4 = *(const float4*)(Bp + k0 * N3);
        As[acol + 0][arow] = a4.x;
        As[acol + 1][arow] = a4.y;
        As[acol + 2][arow] = a4.z;
        As[acol + 3][arow] = a4.w;
        *(float4*)&Bs[brow][bcol] = b4;
        __syncthreads();
#pragma unroll
        for (int kk = 0; kk < 8; kk++) {
            float af[8], bf[8];
#pragma unroll
            for (int i = 0; i < 8; i++) af[i] = As[kk][tr + i];
#pragma unroll
            for (int j = 0; j < 8; j++) bf[j] = Bs[kk][tc + j];
#pragma unroll
            for (int i = 0; i < 8; i++)
#pragma unroll
                for (int j = 0; j < 8; j++) acc[i][j] += af[i] * bf[j];
        }
        __syncthreads();
    }

    // Epilogue: bias + scatter to q/k/v in [B,H,T,D]
#pragma unroll
    for (int i = 0; i < 8; i++) {
        const int m = bm + tr + i;
        const int b = m >> 11;           // /T
        const int t = m & (Tsz - 1);
#pragma unroll
        for (int j = 0; j < 8; j++) {
            const int n = bn + tc + j;
            const float val = acc[i][j] + bias[n];
            const int sec = n >> 10;     // 0=q,1=k,2=v
            const int c2 = n & 1023;
            const int h = c2 >> 6;
            const int d = c2 & 63;
            float* dst = (sec == 0) ? g_q : (sec == 1) ? g_k : g_v;
            dst[((b * Hn + h) * Tsz + t) * Dh + d] = val;
        }
    }
}

// ---------------------------------------------------------------------------
// GEMM 2: out = y @ w_proj + b_proj
// ---------------------------------------------------------------------------
__global__ __launch_bounds__(256) void proj_gemm(const float* __restrict__ Bw,
                                                 const float* __restrict__ bias,
                                                 float* __restrict__ out)
{
    __shared__ float As[8][128];
    __shared__ float Bs[8][128];

    const int tid = threadIdx.x;
    const int bm = blockIdx.y * 128;
    const int bn = blockIdx.x * 128;
    const int tr = (tid >> 4) * 8;
    const int tc = (tid & 15) * 8;

    float acc[8][8];
#pragma unroll
    for (int i = 0; i < 8; i++)
#pragma unroll
        for (int j = 0; j < 8; j++) acc[i][j] = 0.f;

    const int arow = tid >> 1;
    const int acol = (tid & 1) * 4;
    const int brow = tid >> 5;
    const int bcol = (tid & 31) * 4;

    const float* Ap = g_y + (bm + arow) * Csz + acol;
    const float* Bp = Bw + brow * Csz + bn + bcol;

    for (int k0 = 0; k0 < Csz; k0 += 8) {
        float4 a4 = *(const float4*)(Ap + k0);
        float4 b4 = *(const float4*)(Bp + k0 * Csz);
        As[acol + 0][arow] = a4.x;
        As[acol + 1][arow] = a4.y;
        As[acol + 2][arow] = a4.z;
        As[acol + 3][arow] = a4.w;
        *(float4*)&Bs[brow][bcol] = b4;
        __syncthreads();
#pragma unroll
        for (int kk = 0; kk < 8; kk++) {
            float af[8], bf[8];
#pragma unroll
            for (int i = 0; i < 8; i++) af[i] = As[kk][tr + i];
#pragma unroll
            for (int j = 0; j < 8; j++) bf[j] = Bs[kk][tc + j];
#pragma unroll
            for (int i = 0; i < 8; i++)
#pragma unroll
                for (int j = 0; j < 8; j++) acc[i][j] += af[i] * bf[j];
        }
        __syncthreads();
    }

#pragma unroll
    for (int i = 0; i < 8; i++) {
        const int m = bm + tr + i;
#pragma unroll
        for (int j = 0; j < 8; j++) {
            const int n = bn + tc + j;
            out[m * Csz + n] = acc[i][j] + bias[n];
        }
    }
}

// ---------------------------------------------------------------------------
// Flash attention (fp32, causal). Q tile 64, K tile 64, 256 threads,
// per-thread 4x4 micro-tiles. P written back into the K smem tile (aliased).
// Smem: Qs[64][64] + Ks[64][65] + Vs[64][64] = 49408 B (dynamic).
// ---------------------------------------------------------------------------
extern __shared__ float sm_attn[];

__global__ __launch_bounds__(256) void attn_kernel()
{
    float* Qs = sm_attn;                 // [64][64], pre-scaled by 1/8
    float* Ks = sm_attn + 64 * 64;       // [64][65]; later holds P
    float* Vs = Ks + 64 * 65;            // [64][64]

    const int head = blockIdx.y;         // b*H + h
    const int qt = blockIdx.x;           // query tile
    const float* Qg = g_q + head * (Tsz * Dh);
    const float* Kg = g_k + head * (Tsz * Dh);
    const float* Vg = g_v + head * (Tsz * Dh);

    const int tid = threadIdx.x;
    const int rg = tid >> 4;             // 0..15 row group
    const int cg = tid & 15;             // 0..15 col group
    const int r0 = rg * 4;
    const int c0 = cg * 4;

    float m_i[4], l_i[4], o[4][4];
#pragma unroll
    for (int i = 0; i < 4; i++) {
        m_i[i] = -1e30f;
        l_i[i] = 0.f;
#pragma unroll
        for (int j = 0; j < 4; j++) o[i][j] = 0.f;
    }

    // Load Q tile (scale folded in: 1/sqrt(64) = 0.125)
    for (int i = tid; i < 64 * 64; i += 256) {
        const int r = i >> 6, d = i & 63;
        Qs[r * 64 + d] = Qg[(qt * 64 + r) * 64 + d] * 0.125f;
    }

    for (int kt = 0; kt <= qt; kt++) {
        __syncthreads();   // prior PV reads of Ks/Vs done; Q loaded (first iter)
        for (int i = tid; i < 64 * 64; i += 256) {
            const int r = i >> 6, d = i & 63;
            Ks[r * 65 + d] = Kg[(kt * 64 + r) * 64 + d];
            Vs[r * 64 + d] = Vg[(kt * 64 + r) * 64 + d];
        }
        __syncthreads();

        // S = Q @ K^T (32x... 64x64 tile, 4x4 per thread)
        float s[4][4];
#pragma unroll
        for (int i = 0; i < 4; i++)
#pragma unroll
            for (int j = 0; j < 4; j++) s[i][j] = 0.f;

        for (int dd = 0; dd < 64; dd++) {
            float af[4], bf[4];
#pragma unroll
            for (int i = 0; i < 4; i++) af[i] = Qs[(r0 + i) * 64 + dd];
#pragma unroll
            for (int j = 0; j < 4; j++) bf[j] = Ks[(c0 + j) * 65 + dd];
#pragma unroll
            for (int i = 0; i < 4; i++)
#pragma unroll
                for (int j = 0; j < 4; j++) s[i][j] += af[i] * bf[j];
        }

        // Causal mask (only the diagonal tile needs it)
        if (kt == qt) {
#pragma unroll
            for (int i = 0; i < 4; i++)
#pragma unroll
                for (int j = 0; j < 4; j++)
                    if (c0 + j > r0 + i) s[i][j] = -1e30f;
        }

        __syncthreads();   // everyone done reading Ks -> safe to overwrite as P

        // Online softmax; row groups span 16 consecutive lanes (half-warp)
#pragma unroll
        for (int i = 0; i < 4; i++) {
            float tmax = s[i][0];
#pragma unroll
            for (int j = 1; j < 4; j++) tmax = fmaxf(tmax, s[i][j]);
#pragma unroll
            for (int off = 1; off < 16; off <<= 1)
                tmax = fmaxf(tmax, __shfl_xor_sync(0xffffffffu, tmax, off));

            const float mnew = fmaxf(m_i[i], tmax);
            const float sc = __expf(m_i[i] - mnew);
            m_i[i] = mnew;

            float tsum = 0.f;
#pragma unroll
            for (int j = 0; j < 4; j++) {
                const float p = __expf(s[i][j] - mnew);
                s[i][j] = p;
                tsum += p;
            }
#pragma unroll
            for (int off = 1; off < 16; off <<= 1)
                tsum += __shfl_xor_sync(0xffffffffu, tsum, off);

            l_i[i] = l_i[i] * sc + tsum;
#pragma unroll
            for (int j = 0; j < 4; j++) {
                o[i][j] *= sc;
                Ks[(r0 + i) * 65 + (c0 + j)] = s[i][j];   // P tile
            }
        }
        __syncthreads();

        // O += P @ V
        for (int kk = 0; kk < 64; kk++) {
            float af[4], bf[4];
#pragma unroll
            for (int i = 0; i < 4; i++) af[i] = Ks[(r0 + i) * 65 + kk];
#pragma unroll
            for (int j = 0; j < 4; j++) bf[j] = Vs[kk * 64 + c0 + j];
#pragma unroll
            for (int i = 0; i < 4; i++)
#pragma unroll
                for (int j = 0; j < 4; j++) o[i][j] += af[i] * bf[j];
        }
    }

    // Write y in [B,T,C] (head h occupies cols h*64..h*64+63)
    const int b = head >> 4;
    const int h = head & 15;
#pragma unroll
    for (int i = 0; i < 4; i++) {
        const int t = qt * 64 + r0 + i;
        const float inv = 1.f / l_i[i];
#pragma unroll
        for (int j = 0; j < 4; j++)
            g_y[(b * Tsz + t) * Csz + h * 64 + c0 + j] = o[i][j] * inv;
    }
}

// ---------------------------------------------------------------------------

extern "C" void kernel_launch(void* const* d_in, const int* in_sizes, int n_in,
                              void* d_out, int out_size)
{
    (void)in_sizes; (void)n_in; (void)out_size;
    const float* x      = (const float*)d_in[0];
    const float* w_attn = (const float*)d_in[1];
    const float* b_attn = (const float*)d_in[2];
    const float* w_proj = (const float*)d_in[3];
    const float* b_proj = (const float*)d_in[4];
    float* out = (float*)d_out;

    // 49408 B dynamic smem (> 48KB default) — attribute set is idempotent,
    // executes eagerly (not a stream op), safe under graph capture.
    static const size_t ATTN_SMEM = (64 * 64 + 64 * 65 + 64 * 64) * sizeof(float);
    cudaFuncSetAttribute(attn_kernel,
                         cudaFuncAttributeMaxDynamicSharedMemorySize,
                         (int)ATTN_SMEM);

    qkv_gemm<<<dim3(N3 / 128, BT / 128), 256>>>(x, w_attn, b_attn);
    attn_kernel<<<dim3(Tsz / 64, Bsz * Hn), 256, ATTN_SMEM>>>();
    proj_gemm<<<dim3(Csz / 128, BT / 128), 256>>>(w_proj, b_proj, out);
}